// round 13
// baseline (speedup 1.0000x reference)
#include <cuda_runtime.h>
#include <cuda_bf16.h>
#include <cuda_fp16.h>
#include <cstdint>
#include <cstddef>

// ============================================================================
// Problem constants: B=4096, D=512, 2B=8192 rows, temperature 0.1
// ============================================================================
#define B_ROWS 4096
#define DIM    512
#define NROWS  8192
#define NTILES 64            // 64 row-tiles of 128
#define NPAIRS 2080          // upper triangle incl diagonal
#define GRID_G 152           // GB300 SM count (1 persistent CTA per SM)

// Scratch (device globals — no allocation allowed)
__device__ __align__(128) uint8_t g_Fq[NROWS * DIM];  // normalized feats, e4m3*16
__device__ float g_acc[NTILES * NTILES * 128];  // [I][J][r] partial exp-sums
__device__ float g_pos[NROWS];                  // positive-pair dot (unscaled)
__device__ float g_bsum[NTILES];                // per-rowtile NLL partials
__device__ int   g_bar_cnt = 0;                 // global barrier arrival counter
__device__ int   g_bar_go  = 0;                 // global barrier release phase
__device__ int   g_exit    = 0;                 // exit counter (final reduce)

// ============================================================================
// Arch-neutral PTX helpers (ptxas target is plain sm_103: no 'a' features)
// ============================================================================
static __device__ __forceinline__ uint32_t smem_u32(const void* p) {
    uint32_t a;
    asm("{ .reg .u64 t; cvta.to.shared.u64 t, %1; cvt.u32.u64 %0, t; }" : "=r"(a) : "l"(p));
    return a;
}
static __device__ __forceinline__ void ldsm4(uint32_t* r, uint32_t addr) {
    asm volatile("ldmatrix.sync.aligned.m8n8.x4.shared.b16 {%0,%1,%2,%3}, [%4];"
        : "=r"(r[0]), "=r"(r[1]), "=r"(r[2]), "=r"(r[3]) : "r"(addr));
}
// FP8 MMA: m16n8k32 e4m3 x e4m3 -> f32 (PTX ISA, sm_89+, no 'a' feature).
static __device__ __forceinline__ void mma_fp8(float* c, const uint32_t* a,
                                               uint32_t b0, uint32_t b1) {
    asm volatile(
        "mma.sync.aligned.m16n8k32.row.col.f32.e4m3.e4m3.f32 "
        "{%0,%1,%2,%3}, {%4,%5,%6,%7}, {%8,%9}, {%0,%1,%2,%3};"
        : "+f"(c[0]), "+f"(c[1]), "+f"(c[2]), "+f"(c[3])
        : "r"(a[0]), "r"(a[1]), "r"(a[2]), "r"(a[3]), "r"(b0), "r"(b1));
}
// pack two floats -> two e4m3 bytes (hi goes to byte1, lo to byte0)
static __device__ __forceinline__ uint16_t cvt_e4m3x2(float hi, float lo) {
    uint16_t r;
    asm("cvt.rn.satfinite.e4m3x2.f32 %0, %1, %2;" : "=h"(r) : "f"(hi), "f"(lo));
    return r;
}
static __device__ __forceinline__ void cp16(uint32_t dst, const void* src) {
    asm volatile("cp.async.cg.shared.global [%0], [%1], 16;" :: "r"(dst), "l"(src));
}
#define CP_COMMIT() asm volatile("cp.async.commit_group;" ::: "memory")
#define CP_WAIT2()  asm volatile("cp.async.wait_group 2;" ::: "memory")
static __device__ __forceinline__ float ex2f(float x) {
    float y; asm("ex2.approx.ftz.f32 %0, %1;" : "=f"(y) : "f"(x)); return y;
}

// Device-wide barrier. Valid because all GRID_G CTAs are co-resident
// (grid == SM count, 1 CTA/SM at this smem footprint). Counter is reset by
// the releasing CTA; the phase flag is reset by the last exiting CTA so the
// kernel is graph-replay safe.
static __device__ __forceinline__ void gbar(int phase) {
    __syncthreads();
    if (threadIdx.x == 0) {
        __threadfence();
        int old = atomicAdd(&g_bar_cnt, 1);
        if (old == GRID_G - 1) {
            atomicExch(&g_bar_cnt, 0);
            __threadfence();
            atomicExch(&g_bar_go, phase);
        }
        while (*(volatile int*)&g_bar_go < phase) { __nanosleep(64); }
        __threadfence();
    }
    __syncthreads();
}

// ============================================================================
// SMEM: 4-stage ring; stage = A(128 rows x 128 fp8, 144B padded rows) + B same.
// One stage covers K=128 -> 4 stages per 128x128 tile.
// ============================================================================
static constexpr int RSTRIDE = 144;             // bytes per K-slice row
static constexpr int STG_B   = 18432;           // B offset within a stage
static constexpr int STG     = 36864;           // stage bytes
static constexpr int SM_REDR = 4 * STG;         // 147456: 2x128 floats
static constexpr int SM_REDC = SM_REDR + 1024;  // 4x128 floats
static constexpr int SMEM_BYTES = SM_REDC + 2048;  // 150528

// quantization constants: q = e4m3(16 * f)  ->  acc = 256 * dot
static constexpr float QSCL  = 16.0f;
static constexpr float INVQ2 = 1.0f / 256.0f;
static constexpr float EX2C  = 14.426950408889634f / 256.0f;  // 10/ln2/256

// ============================================================================
// Fused persistent kernel: normalize -> barrier -> symmetric GEMM ->
// barrier -> distributed NLL reduce -> last-CTA final mean.
// ============================================================================
__global__ void __launch_bounds__(256, 1) infonce_fused_kernel(
    const float* __restrict__ f1, const float* __restrict__ f2,
    float* __restrict__ out)
{
    extern __shared__ __align__(1024) char smem[];
    const uint32_t sb = smem_u32(smem);
    const int tid  = threadIdx.x;
    const int lane = tid & 31;
    const int wid  = tid >> 5;
    const int cb   = blockIdx.x;

    // ================= Phase 0: L2-normalize + e4m3 quantize ================
    {
        for (int row = cb * 8 + wid; row < NROWS; row += GRID_G * 8) {
            const float* src = (row < B_ROWS) ? (f1 + (size_t)row * DIM)
                                              : (f2 + (size_t)(row - B_ROWS) * DIM);
            float4 v[4];
            float ss = 0.0f;
            #pragma unroll
            for (int i = 0; i < 4; i++) {
                v[i] = ((const float4*)src)[lane + 32 * i];
                ss += v[i].x * v[i].x + v[i].y * v[i].y
                    + v[i].z * v[i].z + v[i].w * v[i].w;
            }
            #pragma unroll
            for (int o = 16; o > 0; o >>= 1) ss += __shfl_xor_sync(0xffffffffu, ss, o);
            const float s = QSCL / fmaxf(sqrtf(ss), 1e-12f);
            uint32_t* dst = (uint32_t*)(g_Fq + (size_t)row * DIM);
            #pragma unroll
            for (int i = 0; i < 4; i++) {
                uint16_t lo = cvt_e4m3x2(v[i].y * s, v[i].x * s);
                uint16_t hi = cvt_e4m3x2(v[i].w * s, v[i].z * s);
                dst[lane + 32 * i] = (uint32_t)lo | ((uint32_t)hi << 16);
            }
        }
    }
    gbar(1);

    // ================= Phase 1: symmetric streaming-softmax GEMM ============
    {
        const int wm = wid >> 1;               // 0..3 : 32-row band
        const int wn = wid & 1;                // 0..1 : 64-col band

        // my contiguous chunk of tile pairs: 2080 = 152*13 + 104
        const int cnt = 13 + (cb < 104 ? 1 : 0);
        int start = cb * 13 + (cb < 104 ? cb : 104);
        int ci = 0;
        { int t = start; while (t >= NTILES - ci) { t -= NTILES - ci; ci++; } start = t; }
        int cj = ci + start;                   // compute cursor (ci,cj)
        int li = ci, lj = cj;                  // loader cursor
        const int NS = cnt * 4;                // 4 K-stages per tile

        const uint32_t aoff = (uint32_t)(
            (wm * 32 + (lane & 7) + ((lane >> 3) & 1) * 8) * RSTRIDE
            + (lane >> 4) * 16);
        const uint32_t boff = (uint32_t)(STG_B
            + (wn * 64 + (lane & 7) + (lane >> 4) * 8) * RSTRIDE
            + ((lane >> 3) & 1) * 16);

        float acc[2][8][4];
        #pragma unroll
        for (int mt = 0; mt < 2; mt++)
            #pragma unroll
            for (int nt = 0; nt < 8; nt++)
                #pragma unroll
                for (int q = 0; q < 4; q++) acc[mt][nt][q] = 0.0f;

        auto issue = [&](int gs) {
            const int kc = gs & 3;             // K-slice 0..3 (128 bytes each)
            const uint32_t stb = sb + (uint32_t)((gs & 3) * STG);
            const uint8_t* pa = g_Fq + ((size_t)li << 7) * DIM + kc * 128;
            const uint8_t* pb = g_Fq + ((size_t)lj << 7) * DIM + kc * 128;
            #pragma unroll
            for (int i = 0; i < 4; i++) {
                int idx = tid + (i << 8);      // 0..1023
                int r = idx >> 3, ck = idx & 7;
                cp16(stb + (uint32_t)(r * RSTRIDE + ck * 16),
                     pa + (size_t)r * DIM + ck * 16);
            }
            #pragma unroll
            for (int i = 0; i < 4; i++) {
                int idx = tid + (i << 8);
                int r = idx >> 3, ck = idx & 7;
                cp16(stb + (uint32_t)(STG_B + r * RSTRIDE + ck * 16),
                     pb + (size_t)r * DIM + ck * 16);
            }
            if (kc == 3) { lj++; if (lj == NTILES) { li++; lj = li; } }
        };

        for (int p = 0; p < 3; p++) { issue(p); CP_COMMIT(); }   // NS >= 52

        float* red_r = (float*)(smem + SM_REDR);
        float* red_c = (float*)(smem + SM_REDC);

        for (int gs = 0; gs < NS; gs++) {
            CP_WAIT2();                          // stage gs complete (this thread)
            __syncthreads();                     // visible to all; ring slot free
            if (gs + 3 < NS) issue(gs + 3);
            CP_COMMIT();

            const uint32_t stb = sb + (uint32_t)((gs & 3) * STG);
            #pragma unroll
            for (int ks = 0; ks < 4; ks++) {     // 4 x k32
                uint32_t a[2][4], b[4][4];
                ldsm4(a[0], stb + aoff + (uint32_t)(ks * 32));
                ldsm4(a[1], stb + aoff + 2304u + (uint32_t)(ks * 32)); // +16 rows
                #pragma unroll
                for (int p = 0; p < 4; p++)
                    ldsm4(b[p], stb + boff + (uint32_t)(p * 2304 + ks * 32));
                #pragma unroll
                for (int mt = 0; mt < 2; mt++)
                    #pragma unroll
                    for (int p = 0; p < 4; p++) {
                        mma_fp8(acc[mt][2 * p],     a[mt], b[p][0], b[p][1]);
                        mma_fp8(acc[mt][2 * p + 1], a[mt], b[p][2], b[p][3]);
                    }
            }

            if ((gs & 3) == 3) {
                // ===== epilogue for tile (ci,cj): exp + row/col partial sums ==
                const bool isdiag = (ci == cj);
                const bool ispos  = (cj == ci + 32);    // label tile (i^4096)
                float rs[4] = {0.f, 0.f, 0.f, 0.f};
                float cs[16];
                #pragma unroll
                for (int i = 0; i < 16; i++) cs[i] = 0.f;
                #pragma unroll
                for (int mt = 0; mt < 2; mt++)
                    #pragma unroll
                    for (int nt = 0; nt < 8; nt++)
                        #pragma unroll
                        for (int q = 0; q < 4; q++) {
                            int rl = wm * 32 + mt * 16 + ((q >> 1) << 3) + (lane >> 2);
                            int cl = wn * 64 + nt * 8 + ((lane & 3) << 1) + (q & 1);
                            float d = acc[mt][nt][q];       // dot * 256
                            acc[mt][nt][q] = 0.0f;
                            float e = ex2f(d * EX2C);       // exp(10*dot)
                            bool dg = (rl == cl);
                            if (!(isdiag && dg)) {
                                rs[mt * 2 + (q >> 1)] += e;
                                cs[nt * 2 + (q & 1)]  += e;
                            }
                            if (ispos && dg) {              // symmetric positive
                                g_pos[(ci << 7) + rl] = d * INVQ2;
                                g_pos[(cj << 7) + cl] = d * INVQ2;
                            }
                        }
                #pragma unroll
                for (int i = 0; i < 4; i++) {
                    rs[i] += __shfl_xor_sync(0xffffffffu, rs[i], 1);
                    rs[i] += __shfl_xor_sync(0xffffffffu, rs[i], 2);
                }
                #pragma unroll
                for (int i = 0; i < 16; i++) {
                    cs[i] += __shfl_xor_sync(0xffffffffu, cs[i], 4);
                    cs[i] += __shfl_xor_sync(0xffffffffu, cs[i], 8);
                    cs[i] += __shfl_xor_sync(0xffffffffu, cs[i], 16);
                }
                if ((lane & 3) == 0) {
                    #pragma unroll
                    for (int i = 0; i < 4; i++)
                        red_r[wn * 128 + wm * 32 + (i >> 1) * 16 + (i & 1) * 8
                              + (lane >> 2)] = rs[i];
                }
                if (lane < 4) {
                    #pragma unroll
                    for (int i = 0; i < 16; i++)
                        red_c[wm * 128 + wn * 64 + (i >> 1) * 8 + lane * 2
                              + (i & 1)] = cs[i];
                }
                __syncthreads();
                if (tid < 128) {
                    float rsum = red_r[tid] + red_r[128 + tid];
                    g_acc[((ci << 6) + cj) * 128 + tid] = rsum;      // rows of I
                    if (!isdiag) {
                        float csum = red_c[tid] + red_c[128 + tid]
                                   + red_c[256 + tid] + red_c[384 + tid];
                        g_acc[((cj << 6) + ci) * 128 + tid] = csum;  // rows of J
                    }
                }
                cj++; if (cj == NTILES) { ci++; cj = ci; }
                // next loop-top __syncthreads protects red_* reuse
            }
        }
    }
    gbar(2);

    // ================= Phase 2: distributed NLL reduce ======================
    float* sm = (float*)smem;                  // smem free after barrier
    if (cb < NTILES && tid < 128) {
        const float* base = g_acc + (size_t)cb * NTILES * 128 + tid;
        float s = 0.0f;
        #pragma unroll 16
        for (int J = 0; J < NTILES; J++) s += __ldcg(base + J * 128);
        sm[tid] = logf(s) - 10.0f * __ldcg(g_pos + cb * 128 + tid);
    }
    __syncthreads();
    #pragma unroll
    for (int st = 64; st > 0; st >>= 1) {
        if (cb < NTILES && tid < st) sm[tid] += sm[tid + st];
        __syncthreads();
    }
    if (cb < NTILES && tid == 0) g_bsum[cb] = sm[0];

    // ================= Exit: last CTA finishes + resets state ===============
    __syncthreads();
    if (tid == 0) {
        __threadfence();
        int old = atomicAdd(&g_exit, 1);
        if (old == GRID_G - 1) {
            __threadfence();
            volatile float* vb = g_bsum;
            float t = 0.0f;
            for (int i = 0; i < NTILES; i++) t += vb[i];
            out[0] = t * (1.0f / (float)NROWS);
            atomicExch(&g_exit, 0);             // reset for next graph replay
            atomicExch(&g_bar_go, 0);
        }
    }
}

// ============================================================================
// Entry point (graph-capturable: kernel launches only)
// ============================================================================
extern "C" void kernel_launch(void* const* d_in, const int* in_sizes, int n_in,
                              void* d_out, int out_size)
{
    (void)in_sizes; (void)n_in; (void)out_size;
    const float* f1 = (const float*)d_in[0];
    const float* f2 = (const float*)d_in[1];
    float* out = (float*)d_out;

    cudaFuncSetAttribute(infonce_fused_kernel,
                         cudaFuncAttributeMaxDynamicSharedMemorySize, SMEM_BYTES);

    infonce_fused_kernel<<<GRID_G, 256, SMEM_BYTES>>>(f1, f2, out);
}

// round 14
// speedup vs baseline: 1.1145x; 1.1145x over previous
#include <cuda_runtime.h>
#include <cuda_bf16.h>
#include <cstdint>
#include <cstddef>

// ============================================================================
// Problem constants: B=4096, D=512, 2B=8192 rows, temperature 0.1
// ============================================================================
#define B_ROWS 4096
#define DIM    512
#define NROWS  8192
#define NTILES 64            // 64 row-tiles of 128
#define NPAIRS 2080          // upper triangle incl diagonal
#define GRID_G 304           // 2 persistent CTAs per SM (152 SMs)

// Scratch (device globals — no allocation allowed)
__device__ __align__(128) uint8_t g_Fq[NROWS * DIM];  // normalized feats, e4m3*16
__device__ float g_acc[NTILES * NTILES * 128];  // [I][J][r] partial exp-sums
__device__ float g_pos[NROWS];                  // positive-pair dot (unscaled)
__device__ float g_bsum[NTILES];                // per-rowtile NLL partials
__device__ int   g_cnt = 0;                     // last-block counter

// ============================================================================
// Arch-neutral PTX helpers (ptxas target is plain sm_103: no 'a' features)
// ============================================================================
static __device__ __forceinline__ uint32_t smem_u32(const void* p) {
    uint32_t a;
    asm("{ .reg .u64 t; cvta.to.shared.u64 t, %1; cvt.u32.u64 %0, t; }" : "=r"(a) : "l"(p));
    return a;
}
static __device__ __forceinline__ void ldsm4(uint32_t* r, uint32_t addr) {
    asm volatile("ldmatrix.sync.aligned.m8n8.x4.shared.b16 {%0,%1,%2,%3}, [%4];"
        : "=r"(r[0]), "=r"(r[1]), "=r"(r[2]), "=r"(r[3]) : "r"(addr));
}
// FP8 MMA: m16n8k32 e4m3 x e4m3 -> f32 (PTX ISA, sm_89+, no 'a' feature).
static __device__ __forceinline__ void mma_fp8(float* c, const uint32_t* a,
                                               uint32_t b0, uint32_t b1) {
    asm volatile(
        "mma.sync.aligned.m16n8k32.row.col.f32.e4m3.e4m3.f32 "
        "{%0,%1,%2,%3}, {%4,%5,%6,%7}, {%8,%9}, {%0,%1,%2,%3};"
        : "+f"(c[0]), "+f"(c[1]), "+f"(c[2]), "+f"(c[3])
        : "r"(a[0]), "r"(a[1]), "r"(a[2]), "r"(a[3]), "r"(b0), "r"(b1));
}
// pack two floats -> two e4m3 bytes (hi goes to byte1, lo to byte0)
static __device__ __forceinline__ uint16_t cvt_e4m3x2(float hi, float lo) {
    uint16_t r;
    asm("cvt.rn.satfinite.e4m3x2.f32 %0, %1, %2;" : "=h"(r) : "f"(hi), "f"(lo));
    return r;
}
static __device__ __forceinline__ void cp16(uint32_t dst, const void* src) {
    asm volatile("cp.async.cg.shared.global [%0], [%1], 16;" :: "r"(dst), "l"(src));
}
#define CP_COMMIT() asm volatile("cp.async.commit_group;" ::: "memory")
#define CP_WAIT1()  asm volatile("cp.async.wait_group 1;" ::: "memory")
static __device__ __forceinline__ float ex2f(float x) {
    float y; asm("ex2.approx.ftz.f32 %0, %1;" : "=f"(y) : "f"(x)); return y;
}

// ============================================================================
// SMEM: 2-stage ring; stage = A(128 rows x 128 fp8, 144B padded rows) + B same.
// One stage covers K=128 -> 4 stages per 128x128 tile. 76.8KB/CTA -> 2 CTAs/SM.
// ============================================================================
static constexpr int RSTRIDE = 144;             // bytes per K-slice row
static constexpr int STG_B   = 18432;           // B offset within a stage
static constexpr int STG     = 36864;           // stage bytes
static constexpr int SM_REDR = 2 * STG;         // 73728: 2x128 floats
static constexpr int SM_REDC = SM_REDR + 1024;  // 4x128 floats
static constexpr int SMEM_BYTES = SM_REDC + 2048;  // 76800

// quantization constants: q = e4m3(16 * f)  ->  acc = 256 * dot
static constexpr float QSCL  = 16.0f;
static constexpr float INVQ2 = 1.0f / 256.0f;
static constexpr float EX2C  = 14.426950408889634f / 256.0f;  // 10/ln2/256

// ============================================================================
// Kernel 1: L2-normalize + quantize to e4m3 (warp per row, no smem/syncs)
// ============================================================================
__global__ void __launch_bounds__(256) normalize_kernel(
    const float* __restrict__ f1, const float* __restrict__ f2)
{
    const int row  = blockIdx.x * 8 + (threadIdx.x >> 5);   // grid 1024
    const int lane = threadIdx.x & 31;
    const float* src = (row < B_ROWS) ? (f1 + (size_t)row * DIM)
                                      : (f2 + (size_t)(row - B_ROWS) * DIM);
    float4 v[4];
    float ss = 0.0f;
    #pragma unroll
    for (int i = 0; i < 4; i++) {
        v[i] = ((const float4*)src)[lane + 32 * i];
        ss += v[i].x * v[i].x + v[i].y * v[i].y + v[i].z * v[i].z + v[i].w * v[i].w;
    }
    #pragma unroll
    for (int o = 16; o > 0; o >>= 1) ss += __shfl_xor_sync(0xffffffffu, ss, o);
    const float s = QSCL / fmaxf(sqrtf(ss), 1e-12f);
    uint32_t* dst = (uint32_t*)(g_Fq + (size_t)row * DIM);
    #pragma unroll
    for (int i = 0; i < 4; i++) {
        uint16_t lo = cvt_e4m3x2(v[i].y * s, v[i].x * s);   // bytes 0,1
        uint16_t hi = cvt_e4m3x2(v[i].w * s, v[i].z * s);   // bytes 2,3
        dst[lane + 32 * i] = (uint32_t)lo | ((uint32_t)hi << 16);
    }
}

// ============================================================================
// Kernel 2: symmetric streaming-softmax GEMM over upper-triangle tile pairs.
// 304 persistent CTAs (2/SM) x 256 threads; 8 warps in 4(row) x 2(col) grid,
// warp tile 32x64. FP8 mma m16n8k32; 4 K-stages per 128x128 tile.
// 2 CTAs/SM decorrelate barrier/epilogue stalls -> tensor pipe stays fed.
// ============================================================================
__global__ void __launch_bounds__(256, 2) infonce_sym_kernel()
{
    extern __shared__ __align__(1024) char smem[];
    const uint32_t sb = smem_u32(smem);
    const int tid  = threadIdx.x;
    const int lane = tid & 31;
    const int wid  = tid >> 5;
    const int wm   = wid >> 1;                 // 0..3 : 32-row band
    const int wn   = wid & 1;                  // 0..1 : 64-col band

    // ---- my contiguous chunk of tile pairs: 2080 = 304*6 + 256 ----
    const int cb  = blockIdx.x;
    const int cnt = 6 + (cb < 256 ? 1 : 0);
    int start = cb * 6 + (cb < 256 ? cb : 256);
    int ci = 0;
    { int t = start; while (t >= NTILES - ci) { t -= NTILES - ci; ci++; } start = t; }
    int cj = ci + start;                       // compute cursor (ci,cj)
    int li = ci, lj = cj;                      // loader cursor
    const int NS = cnt * 4;                    // 4 K-stages per tile

    // ---- ldmatrix per-thread base byte offsets within a stage ----
    const uint32_t aoff = (uint32_t)(
        (wm * 32 + (lane & 7) + ((lane >> 3) & 1) * 8) * RSTRIDE
        + (lane >> 4) * 16);
    const uint32_t boff = (uint32_t)(STG_B
        + (wn * 64 + (lane & 7) + (lane >> 4) * 8) * RSTRIDE
        + ((lane >> 3) & 1) * 16);

    float acc[2][8][4];
    #pragma unroll
    for (int mt = 0; mt < 2; mt++)
        #pragma unroll
        for (int nt = 0; nt < 8; nt++)
            #pragma unroll
            for (int q = 0; q < 4; q++) acc[mt][nt][q] = 0.0f;

    // ---- stage issue: 2048 x 16B cp.async (8/thread): A rows then B rows ----
    auto issue = [&](int gs) {
        const int kc = gs & 3;                 // K-slice 0..3 (128 bytes each)
        const uint32_t stb = sb + (uint32_t)((gs & 1) * STG);
        const uint8_t* pa = g_Fq + ((size_t)li << 7) * DIM + kc * 128;
        const uint8_t* pb = g_Fq + ((size_t)lj << 7) * DIM + kc * 128;
        #pragma unroll
        for (int i = 0; i < 4; i++) {
            int idx = tid + (i << 8);          // 0..1023
            int r = idx >> 3, ck = idx & 7;
            cp16(stb + (uint32_t)(r * RSTRIDE + ck * 16),
                 pa + (size_t)r * DIM + ck * 16);
        }
        #pragma unroll
        for (int i = 0; i < 4; i++) {
            int idx = tid + (i << 8);
            int r = idx >> 3, ck = idx & 7;
            cp16(stb + (uint32_t)(STG_B + r * RSTRIDE + ck * 16),
                 pb + (size_t)r * DIM + ck * 16);
        }
        if (kc == 3) { lj++; if (lj == NTILES) { li++; lj = li; } }
    };

    issue(0); CP_COMMIT();
    issue(1); CP_COMMIT();                     // NS >= 24

    float* red_r = (float*)(smem + SM_REDR);
    float* red_c = (float*)(smem + SM_REDC);

    for (int gs = 0; gs < NS; gs++) {
        CP_WAIT1();                              // stage gs complete (this thread)
        __syncthreads();                         // visible to all

        const uint32_t stb = sb + (uint32_t)((gs & 1) * STG);
        #pragma unroll
        for (int ks = 0; ks < 4; ks++) {         // 4 x k32
            uint32_t a[2][4], b[4][4];
            ldsm4(a[0], stb + aoff + (uint32_t)(ks * 32));
            ldsm4(a[1], stb + aoff + 2304u + (uint32_t)(ks * 32));  // +16 rows
            #pragma unroll
            for (int p = 0; p < 4; p++)
                ldsm4(b[p], stb + boff + (uint32_t)(p * 2304 + ks * 32));
            #pragma unroll
            for (int mt = 0; mt < 2; mt++)
                #pragma unroll
                for (int p = 0; p < 4; p++) {
                    mma_fp8(acc[mt][2 * p],     a[mt], b[p][0], b[p][1]);
                    mma_fp8(acc[mt][2 * p + 1], a[mt], b[p][2], b[p][3]);
                }
        }

        if ((gs & 3) == 3) {
            // ======= epilogue for tile (ci,cj): exp + row/col partial sums ====
            const bool isdiag = (ci == cj);
            const bool ispos  = (cj == ci + 32);    // label tile (i^4096)
            float rs[4] = {0.f, 0.f, 0.f, 0.f};
            float cs[16];
            #pragma unroll
            for (int i = 0; i < 16; i++) cs[i] = 0.f;

            if (!isdiag && !ispos) {
                // ---- fast path (1984/2080 tiles): no index math, no compares
                #pragma unroll
                for (int mt = 0; mt < 2; mt++)
                    #pragma unroll
                    for (int nt = 0; nt < 8; nt++)
                        #pragma unroll
                        for (int q = 0; q < 4; q++) {
                            float e = ex2f(acc[mt][nt][q] * EX2C);
                            acc[mt][nt][q] = 0.0f;
                            rs[mt * 2 + (q >> 1)] += e;
                            cs[nt * 2 + (q & 1)]  += e;
                        }
            } else {
                // ---- slow path: diagonal mask / positive-pair capture
                #pragma unroll
                for (int mt = 0; mt < 2; mt++)
                    #pragma unroll
                    for (int nt = 0; nt < 8; nt++)
                        #pragma unroll
                        for (int q = 0; q < 4; q++) {
                            int rl = wm * 32 + mt * 16 + ((q >> 1) << 3) + (lane >> 2);
                            int cl = wn * 64 + nt * 8 + ((lane & 3) << 1) + (q & 1);
                            float d = acc[mt][nt][q];       // dot * 256
                            acc[mt][nt][q] = 0.0f;
                            float e = ex2f(d * EX2C);       // exp(10*dot)
                            bool dg = (rl == cl);
                            if (!(isdiag && dg)) {
                                rs[mt * 2 + (q >> 1)] += e;
                                cs[nt * 2 + (q & 1)]  += e;
                            }
                            if (ispos && dg) {              // symmetric positive
                                g_pos[(ci << 7) + rl] = d * INVQ2;
                                g_pos[(cj << 7) + cl] = d * INVQ2;
                            }
                        }
            }
            // row sums: reduce over lane&3 (same rows, different cols)
            #pragma unroll
            for (int i = 0; i < 4; i++) {
                rs[i] += __shfl_xor_sync(0xffffffffu, rs[i], 1);
                rs[i] += __shfl_xor_sync(0xffffffffu, rs[i], 2);
            }
            // col sums: reduce over lane>>2 (same cols, different rows)
            #pragma unroll
            for (int i = 0; i < 16; i++) {
                cs[i] += __shfl_xor_sync(0xffffffffu, cs[i], 4);
                cs[i] += __shfl_xor_sync(0xffffffffu, cs[i], 8);
                cs[i] += __shfl_xor_sync(0xffffffffu, cs[i], 16);
            }
            if ((lane & 3) == 0) {
                #pragma unroll
                for (int i = 0; i < 4; i++)
                    red_r[wn * 128 + wm * 32 + (i >> 1) * 16 + (i & 1) * 8
                          + (lane >> 2)] = rs[i];
            }
            if (lane < 4) {
                #pragma unroll
                for (int i = 0; i < 16; i++)
                    red_c[wm * 128 + wn * 64 + (i >> 1) * 8 + lane * 2
                          + (i & 1)] = cs[i];
            }
            __syncthreads();
            if (tid < 128) {
                float rsum = red_r[tid] + red_r[128 + tid];
                g_acc[((ci << 6) + cj) * 128 + tid] = rsum;          // rows of I
                if (!isdiag) {
                    float csum = red_c[tid] + red_c[128 + tid]
                               + red_c[256 + tid] + red_c[384 + tid];
                    g_acc[((cj << 6) + ci) * 128 + tid] = csum;      // rows of J
                }
            }
            cj++; if (cj == NTILES) { ci++; cj = ci; }
        }

        __syncthreads();                         // ring slot fully consumed
        if (gs + 2 < NS) issue(gs + 2);
        CP_COMMIT();                             // commit every stage (bookkeeping)
    }
}

// ============================================================================
// Kernel 3: per-row NLL + final mean (last block finishes; deterministic)
// ============================================================================
__global__ void __launch_bounds__(128) reduce_kernel(float* __restrict__ out)
{
    const int b = blockIdx.x, r = threadIdx.x;  // 64 blocks x 128 rows
    const float* base = g_acc + (size_t)b * NTILES * 128;
    float s = 0.0f;
    #pragma unroll 16
    for (int J = 0; J < NTILES; J++) s += base[J * 128 + r];
    float nll = logf(s) - 10.0f * g_pos[b * 128 + r];
    __shared__ float sm[128];
    sm[r] = nll;
    __syncthreads();
    #pragma unroll
    for (int st = 64; st > 0; st >>= 1) {
        if (r < st) sm[r] += sm[r + st];
        __syncthreads();
    }
    if (r == 0) {
        g_bsum[b] = sm[0];
        __threadfence();
        int old = atomicAdd(&g_cnt, 1);
        if (old == NTILES - 1) {                // last block: all partials ready
            volatile float* vb = g_bsum;
            float t = 0.0f;
            for (int i = 0; i < NTILES; i++) t += vb[i];
            out[0] = t * (1.0f / (float)NROWS);
            g_cnt = 0;                          // reset for next graph replay
        }
    }
}

// ============================================================================
// Entry point (graph-capturable: kernel launches only)
// ============================================================================
extern "C" void kernel_launch(void* const* d_in, const int* in_sizes, int n_in,
                              void* d_out, int out_size)
{
    (void)in_sizes; (void)n_in; (void)out_size;
    const float* f1 = (const float*)d_in[0];
    const float* f2 = (const float*)d_in[1];
    float* out = (float*)d_out;

    cudaFuncSetAttribute(infonce_sym_kernel,
                         cudaFuncAttributeMaxDynamicSharedMemorySize, SMEM_BYTES);

    normalize_kernel<<<NROWS / 8, 256>>>(f1, f2);
    infonce_sym_kernel<<<GRID_G, 256, SMEM_BYTES>>>();
    reduce_kernel<<<NTILES, 128>>>(out);
}